// round 4
// baseline (speedup 1.0000x reference)
#include <cuda_runtime.h>
#include <math.h>
#include <float.h>

// MultiScaleDynamicFusionGate — GB300 sm_103a — R4
// Warp-autonomous (one warp = one 8-row group), but with streaming
// accumulation instead of register-buffered loads: R3's v1[8]/v2[8] cost
// 64 regs -> 118 total -> occ 23.6%. Forcing 4 blocks/SM doubles resident
// warps so load phases of some warps cover reduce/MLP tails of others.

#define L_DIM 1024

__global__ __launch_bounds__(256, 4) void msdfg_kernel(
    const float* __restrict__ a1, const float* __restrict__ a2,
    const float* __restrict__ W1, const float* __restrict__ b1,
    const float* __restrict__ W2, const float* __restrict__ b2,
    const float* __restrict__ W3, const float* __restrict__ b3,
    const float* __restrict__ sw, float* __restrict__ out)
{
    __shared__ float shW1T[3][8][32];    // [s][f][o]
    __shared__ float shB1[3][32];
    __shared__ float shW2T[3][32][16];   // [s][f][o]
    __shared__ float shB2[3][16];
    __shared__ float shW3[3][16];
    __shared__ float shB3[3];
    __shared__ float shSW[3];
    __shared__ float rs[8][8][8];        // [warp][row][stat]

    const int tid  = threadIdx.x;
    const int w    = tid >> 5;
    const int lane = tid & 31;

    // ---- One-time weight staging ----
    for (int idx = tid; idx < 768; idx += 256) {          // W1 [3][32][8]
        int s = idx >> 8, rem = idx & 255;
        shW1T[s][rem & 7][rem >> 3] = W1[idx];
    }
    for (int idx = tid; idx < 1536; idx += 256) {         // W2 [3][16][32]
        int s = idx >> 9, rem = idx & 511;
        shW2T[s][rem & 31][rem >> 5] = W2[idx];
    }
    if (tid < 96)                 ((float*)shB1)[tid] = b1[tid];
    else if (tid < 144)           ((float*)shB2)[tid - 96]  = b2[tid - 96];
    else if (tid < 192)           ((float*)shW3)[tid - 144] = W3[tid - 144];
    else if (tid < 195)           ((float*)shB3)[tid - 192] = b3[tid - 192];
    else if (tid >= 200 && tid < 203) shSW[tid - 200] = sw[tid - 200];
    __syncthreads();

    const int group = blockIdx.x * 8 + w;                 // 8192 groups
    const long long row0 = (long long)group * 8;

    const float invL  = 1.0f / (float)L_DIM;
    const float invN1 = 1.0f / (float)(L_DIM - 1);

    // ---- Phase 1: per-row stats, streaming accumulation ----
    for (int r = 0; r < 8; r++) {
        const float4* p1 = (const float4*)(a1 + (row0 + r) * (long long)L_DIM);
        const float4* p2 = (const float4*)(a2 + (row0 + r) * (long long)L_DIM);

        // Split accumulators (a/b) shorten dependency chains and let ptxas
        // front-batch the independent loads.
        float s1a = 0.f, s1b = 0.f, q1a = 0.f, q1b = 0.f;
        float mx1 = -FLT_MAX, mn1 = FLT_MAX;
        float s2a = 0.f, s2b = 0.f, q2a = 0.f, q2b = 0.f;
        float mx2 = -FLT_MAX, mn2 = FLT_MAX;

        #pragma unroll
        for (int i = 0; i < 8; i++) {
            float4 v = __ldg(&p1[lane + 32 * i]);
            if (i & 1) { s1b += (v.x + v.y) + (v.z + v.w);
                         q1b += (v.x * v.x + v.y * v.y) + (v.z * v.z + v.w * v.w); }
            else       { s1a += (v.x + v.y) + (v.z + v.w);
                         q1a += (v.x * v.x + v.y * v.y) + (v.z * v.z + v.w * v.w); }
            mx1 = fmaxf(mx1, fmaxf(fmaxf(v.x, v.y), fmaxf(v.z, v.w)));
            mn1 = fminf(mn1, fminf(fminf(v.x, v.y), fminf(v.z, v.w)));
        }
        #pragma unroll
        for (int i = 0; i < 8; i++) {
            float4 v = __ldg(&p2[lane + 32 * i]);
            if (i & 1) { s2b += (v.x + v.y) + (v.z + v.w);
                         q2b += (v.x * v.x + v.y * v.y) + (v.z * v.z + v.w * v.w); }
            else       { s2a += (v.x + v.y) + (v.z + v.w);
                         q2a += (v.x * v.x + v.y * v.y) + (v.z * v.z + v.w * v.w); }
            mx2 = fmaxf(mx2, fmaxf(fmaxf(v.x, v.y), fmaxf(v.z, v.w)));
            mn2 = fminf(mn2, fminf(fminf(v.x, v.y), fminf(v.z, v.w)));
        }

        float s1 = s1a + s1b, q1 = q1a + q1b;
        float s2 = s2a + s2b, q2 = q2a + q2b;

        #pragma unroll
        for (int off = 16; off > 0; off >>= 1) {
            s1 += __shfl_xor_sync(0xffffffffu, s1, off);
            q1 += __shfl_xor_sync(0xffffffffu, q1, off);
            mx1 = fmaxf(mx1, __shfl_xor_sync(0xffffffffu, mx1, off));
            mn1 = fminf(mn1, __shfl_xor_sync(0xffffffffu, mn1, off));
            s2 += __shfl_xor_sync(0xffffffffu, s2, off);
            q2 += __shfl_xor_sync(0xffffffffu, q2, off);
            mx2 = fmaxf(mx2, __shfl_xor_sync(0xffffffffu, mx2, off));
            mn2 = fminf(mn2, __shfl_xor_sync(0xffffffffu, mn2, off));
        }
        if (lane == 0) {
            rs[w][r][0] = s1;
            rs[w][r][1] = sqrtf(fmaxf(0.f, (q1 - s1 * s1 * invL) * invN1));
            rs[w][r][2] = mx1;
            rs[w][r][3] = mn1;
            rs[w][r][4] = s2;
            rs[w][r][5] = sqrtf(fmaxf(0.f, (q2 - s2 * s2 * invL) * invN1));
            rs[w][r][6] = mx2;
            rs[w][r][7] = mn2;
        }
    }
    __syncwarp();

    // ---- Softmax over scale_weights ----
    float w0, w1g, w2g;
    {
        float t0 = shSW[0], t1 = shSW[1], t2 = shSW[2];
        float m  = fmaxf(t0, fmaxf(t1, t2));
        float e0 = __expf(t0 - m), e1 = __expf(t1 - m), e2 = __expf(t2 - m);
        float inv = 1.0f / (e0 + e1 + e2);
        w0 = e0 * inv; w1g = e1 * inv; w2g = e2 * inv;   // ws=2, ws=4, ws=8
    }

    // ---- Phase 2: 7 windows, lane-parallel MLPs ----
    float acc = 0.f;

    #pragma unroll
    for (int wi = 0; wi < 7; wi++) {
        int s, ws, r0;
        float wgt;
        if (wi == 0)      { s = 2; ws = 8; r0 = 0;            wgt = w2g; }
        else if (wi < 3)  { s = 1; ws = 4; r0 = (wi - 1) * 4; wgt = w1g; }
        else              { s = 0; ws = 2; r0 = (wi - 3) * 2; wgt = w0;  }

        const float invws = 1.0f / (float)ws;

        float g[8];
        {
            float sm1 = 0.f, sd1 = 0.f, sx1 = 0.f, sn1 = 0.f;
            float sm2 = 0.f, sd2 = 0.f, sx2 = 0.f, sn2 = 0.f;
            #pragma unroll
            for (int r = 0; r < 8; r++) {
                if (r >= r0 && r < r0 + ws) {
                    sm1 += rs[w][r][0]; sd1 += rs[w][r][1];
                    sx1 += rs[w][r][2]; sn1 += rs[w][r][3];
                    sm2 += rs[w][r][4]; sd2 += rs[w][r][5];
                    sx2 += rs[w][r][6]; sn2 += rs[w][r][7];
                }
            }
            g[0] = sm1 * invL * invws; g[1] = sd1 * invws;
            g[2] = sx1 * invws;        g[3] = sn1 * invws;
            g[4] = sm2 * invL * invws; g[5] = sd2 * invws;
            g[6] = sx2 * invws;        g[7] = sn2 * invws;
        }

        float h1;
        {
            float v = shB1[s][lane];
            #pragma unroll
            for (int f = 0; f < 8; f++) v = fmaf(shW1T[s][f][lane], g[f], v);
            h1 = fmaxf(v, 0.f);
        }
        float h2;
        {
            const int oo = lane & 15;
            float v = shB2[s][oo];
            #pragma unroll
            for (int f = 0; f < 32; f++)
                v = fmaf(shW2T[s][f][oo], __shfl_sync(0xffffffffu, h1, f), v);
            h2 = fmaxf(v, 0.f);
        }
        {
            float part = (lane < 16) ? shW3[s][lane] * h2 : 0.f;
            #pragma unroll
            for (int off = 16; off > 0; off >>= 1)
                part += __shfl_xor_sync(0xffffffffu, part, off);
            float z = __shfl_sync(0xffffffffu, part, 0) + shB3[s];
            float alpha = 1.0f / (1.0f + __expf(-z));
            if (lane >= r0 && lane < r0 + ws)
                acc = fmaf(wgt, alpha, acc);
        }
    }

    if (lane < 8)
        out[row0 + lane] = acc;
}

extern "C" void kernel_launch(void* const* d_in, const int* in_sizes, int n_in,
                              void* d_out, int out_size) {
    const float* a1 = (const float*)d_in[0];
    const float* a2 = (const float*)d_in[1];
    const float* W1 = (const float*)d_in[2];
    const float* b1 = (const float*)d_in[3];
    const float* W2 = (const float*)d_in[4];
    const float* b2 = (const float*)d_in[5];
    const float* W3 = (const float*)d_in[6];
    const float* b3 = (const float*)d_in[7];
    const float* sw = (const float*)d_in[8];
    float* out = (float*)d_out;

    const int groups = out_size / 8;     // 8192
    const int grid   = groups / 8;       // 1024 blocks, 8 warps each
    msdfg_kernel<<<grid, 256>>>(a1, a2, W1, b1, W2, b2, W3, b3, sw, out);
}

// round 5
// speedup vs baseline: 1.1134x; 1.1134x over previous
#include <cuda_runtime.h>
#include <math.h>
#include <float.h>

// MultiScaleDynamicFusionGate — GB300 sm_103a — R5
// Warp-autonomous, 4 rows per warp (8 lanes/row): per-row reduce is a
// 3-level intra-8-lane butterfly reducing 4 rows at once (48 shfls/group
// vs 320 in R3/R4). Loads stay fully coalesced (4x128B line-aligned chunks
// per instruction). High per-warp MLP, no occupancy clamp (R4 lesson).

#define L_DIM 1024

__global__ __launch_bounds__(256) void msdfg_kernel(
    const float* __restrict__ a1, const float* __restrict__ a2,
    const float* __restrict__ W1, const float* __restrict__ b1,
    const float* __restrict__ W2, const float* __restrict__ b2,
    const float* __restrict__ W3, const float* __restrict__ b3,
    const float* __restrict__ sw, float* __restrict__ out)
{
    __shared__ float shW1T[3][8][32];    // [s][f][o]
    __shared__ float shB1[3][32];
    __shared__ float shW2T[3][32][16];   // [s][f][o]
    __shared__ float shB2[3][16];
    __shared__ float shW3[3][16];
    __shared__ float shB3[3];
    __shared__ float shSW[3];
    __shared__ float rs[8][8][8];        // [warp][row][stat]

    const int tid  = threadIdx.x;
    const int w    = tid >> 5;
    const int lane = tid & 31;

    // ---- One-time weight staging ----
    for (int idx = tid; idx < 768; idx += 256) {          // W1 [3][32][8]
        int s = idx >> 8, rem = idx & 255;
        shW1T[s][rem & 7][rem >> 3] = W1[idx];
    }
    for (int idx = tid; idx < 1536; idx += 256) {         // W2 [3][16][32]
        int s = idx >> 9, rem = idx & 511;
        shW2T[s][rem & 31][rem >> 5] = W2[idx];
    }
    if (tid < 96)                 ((float*)shB1)[tid] = b1[tid];
    else if (tid < 144)           ((float*)shB2)[tid - 96]  = b2[tid - 96];
    else if (tid < 192)           ((float*)shW3)[tid - 144] = W3[tid - 144];
    else if (tid < 195)           ((float*)shB3)[tid - 192] = b3[tid - 192];
    else if (tid >= 200 && tid < 203) shSW[tid - 200] = sw[tid - 200];
    __syncthreads();

    const int group = blockIdx.x * 8 + w;                 // 8192 groups
    const long long row0 = (long long)group * 8;

    const float invL  = 1.0f / (float)L_DIM;
    const float invN1 = 1.0f / (float)(L_DIM - 1);

    const int rsub = lane >> 3;          // which of 4 rows this lane helps (0..3)
    const int lr   = lane & 7;           // lane within the 8-lane row team

    // ---- Phase 1: two passes, each pass = 4 rows reduced simultaneously ----
    #pragma unroll
    for (int pass = 0; pass < 2; pass++) {
        const int row = pass * 4 + rsub;
        const float4* p1 = (const float4*)(a1 + (row0 + row) * (long long)L_DIM) + lr;
        const float4* p2 = (const float4*)(a2 + (row0 + row) * (long long)L_DIM) + lr;

        float s1a = 0.f, s1b = 0.f, q1a = 0.f, q1b = 0.f;
        float mx1 = -FLT_MAX, mn1 = FLT_MAX;
        float s2a = 0.f, s2b = 0.f, q2a = 0.f, q2b = 0.f;
        float mx2 = -FLT_MAX, mn2 = FLT_MAX;

        // 1024 floats/row over 8 lanes*4 floats = 32 float4 per lane per tensor
        #pragma unroll 8
        for (int i = 0; i < 32; i++) {
            float4 v = p1[8 * i];
            if (i & 1) { s1b += (v.x + v.y) + (v.z + v.w);
                         q1b += (v.x * v.x + v.y * v.y) + (v.z * v.z + v.w * v.w); }
            else       { s1a += (v.x + v.y) + (v.z + v.w);
                         q1a += (v.x * v.x + v.y * v.y) + (v.z * v.z + v.w * v.w); }
            mx1 = fmaxf(mx1, fmaxf(fmaxf(v.x, v.y), fmaxf(v.z, v.w)));
            mn1 = fminf(mn1, fminf(fminf(v.x, v.y), fminf(v.z, v.w)));
        }
        #pragma unroll 8
        for (int i = 0; i < 32; i++) {
            float4 v = p2[8 * i];
            if (i & 1) { s2b += (v.x + v.y) + (v.z + v.w);
                         q2b += (v.x * v.x + v.y * v.y) + (v.z * v.z + v.w * v.w); }
            else       { s2a += (v.x + v.y) + (v.z + v.w);
                         q2a += (v.x * v.x + v.y * v.y) + (v.z * v.z + v.w * v.w); }
            mx2 = fmaxf(mx2, fmaxf(fmaxf(v.x, v.y), fmaxf(v.z, v.w)));
            mn2 = fminf(mn2, fminf(fminf(v.x, v.y), fminf(v.z, v.w)));
        }

        float s1 = s1a + s1b, q1 = q1a + q1b;
        float s2 = s2a + s2b, q2 = q2a + q2b;

        // 3-level butterfly within each 8-lane group (reduces 4 rows at once)
        #pragma unroll
        for (int off = 4; off > 0; off >>= 1) {
            s1 += __shfl_xor_sync(0xffffffffu, s1, off);
            q1 += __shfl_xor_sync(0xffffffffu, q1, off);
            mx1 = fmaxf(mx1, __shfl_xor_sync(0xffffffffu, mx1, off));
            mn1 = fminf(mn1, __shfl_xor_sync(0xffffffffu, mn1, off));
            s2 += __shfl_xor_sync(0xffffffffu, s2, off);
            q2 += __shfl_xor_sync(0xffffffffu, q2, off);
            mx2 = fmaxf(mx2, __shfl_xor_sync(0xffffffffu, mx2, off));
            mn2 = fminf(mn2, __shfl_xor_sync(0xffffffffu, mn2, off));
        }
        if (lr == 0) {
            rs[w][row][0] = s1;
            rs[w][row][1] = sqrtf(fmaxf(0.f, (q1 - s1 * s1 * invL) * invN1));
            rs[w][row][2] = mx1;
            rs[w][row][3] = mn1;
            rs[w][row][4] = s2;
            rs[w][row][5] = sqrtf(fmaxf(0.f, (q2 - s2 * s2 * invL) * invN1));
            rs[w][row][6] = mx2;
            rs[w][row][7] = mn2;
        }
    }
    __syncwarp();

    // ---- Softmax over scale_weights ----
    float w0, w1g, w2g;
    {
        float t0 = shSW[0], t1 = shSW[1], t2 = shSW[2];
        float m  = fmaxf(t0, fmaxf(t1, t2));
        float e0 = __expf(t0 - m), e1 = __expf(t1 - m), e2 = __expf(t2 - m);
        float inv = 1.0f / (e0 + e1 + e2);
        w0 = e0 * inv; w1g = e1 * inv; w2g = e2 * inv;   // ws=2, ws=4, ws=8
    }

    // ---- Phase 2: 7 windows, lane-parallel MLPs ----
    float acc = 0.f;

    #pragma unroll
    for (int wi = 0; wi < 7; wi++) {
        int s, ws, r0;
        float wgt;
        if (wi == 0)      { s = 2; ws = 8; r0 = 0;            wgt = w2g; }
        else if (wi < 3)  { s = 1; ws = 4; r0 = (wi - 1) * 4; wgt = w1g; }
        else              { s = 0; ws = 2; r0 = (wi - 3) * 2; wgt = w0;  }

        const float invws = 1.0f / (float)ws;

        float g[8];
        {
            float sm1 = 0.f, sd1 = 0.f, sx1 = 0.f, sn1 = 0.f;
            float sm2 = 0.f, sd2 = 0.f, sx2 = 0.f, sn2 = 0.f;
            #pragma unroll
            for (int r = 0; r < 8; r++) {
                if (r >= r0 && r < r0 + ws) {
                    sm1 += rs[w][r][0]; sd1 += rs[w][r][1];
                    sx1 += rs[w][r][2]; sn1 += rs[w][r][3];
                    sm2 += rs[w][r][4]; sd2 += rs[w][r][5];
                    sx2 += rs[w][r][6]; sn2 += rs[w][r][7];
                }
            }
            g[0] = sm1 * invL * invws; g[1] = sd1 * invws;
            g[2] = sx1 * invws;        g[3] = sn1 * invws;
            g[4] = sm2 * invL * invws; g[5] = sd2 * invws;
            g[6] = sx2 * invws;        g[7] = sn2 * invws;
        }

        float h1;
        {
            float v = shB1[s][lane];
            #pragma unroll
            for (int f = 0; f < 8; f++) v = fmaf(shW1T[s][f][lane], g[f], v);
            h1 = fmaxf(v, 0.f);
        }
        float h2;
        {
            const int oo = lane & 15;
            float v = shB2[s][oo];
            #pragma unroll
            for (int f = 0; f < 32; f++)
                v = fmaf(shW2T[s][f][oo], __shfl_sync(0xffffffffu, h1, f), v);
            h2 = fmaxf(v, 0.f);
        }
        {
            float part = (lane < 16) ? shW3[s][lane] * h2 : 0.f;
            #pragma unroll
            for (int off = 16; off > 0; off >>= 1)
                part += __shfl_xor_sync(0xffffffffu, part, off);
            float z = __shfl_sync(0xffffffffu, part, 0) + shB3[s];
            float alpha = 1.0f / (1.0f + __expf(-z));
            if (lane >= r0 && lane < r0 + ws)
                acc = fmaf(wgt, alpha, acc);
        }
    }

    if (lane < 8)
        out[row0 + lane] = acc;
}

extern "C" void kernel_launch(void* const* d_in, const int* in_sizes, int n_in,
                              void* d_out, int out_size) {
    const float* a1 = (const float*)d_in[0];
    const float* a2 = (const float*)d_in[1];
    const float* W1 = (const float*)d_in[2];
    const float* b1 = (const float*)d_in[3];
    const float* W2 = (const float*)d_in[4];
    const float* b2 = (const float*)d_in[5];
    const float* W3 = (const float*)d_in[6];
    const float* b3 = (const float*)d_in[7];
    const float* sw = (const float*)d_in[8];
    float* out = (float*)d_out;

    const int groups = out_size / 8;     // 8192
    const int grid   = groups / 8;       // 1024 blocks, 8 warps each
    msdfg_kernel<<<grid, 256>>>(a1, a2, W1, b1, W2, b2, W3, b3, sw, out);
}

// round 6
// speedup vs baseline: 1.2341x; 1.1084x over previous
#include <cuda_runtime.h>
#include <cuda_pipeline.h>
#include <math.h>
#include <float.h>

// MultiScaleDynamicFusionGate — GB300 sm_103a — R6
// Per-lane cp.async (LDGSTS) double-buffered pipeline: each warp always has
// the next 4KB chunk in flight while reducing the current one, so DRAM never
// drains during reduce/MLP phases (R3-R5 were pinned at DRAM=64% because
// loads and compute were serialized per warp).
//
// Lane j async-copies exactly the bytes lane j later reads -> no cross-lane
// hazards, zero syncs inside the chunk loop.

#define L_DIM 1024

extern __shared__ float stage_smem[];   // [8 warps][2 stages][1024 floats] = 64KB

__global__ __launch_bounds__(256) void msdfg_kernel(
    const float* __restrict__ a1, const float* __restrict__ a2,
    const float* __restrict__ W1, const float* __restrict__ b1,
    const float* __restrict__ W2, const float* __restrict__ b2,
    const float* __restrict__ W3, const float* __restrict__ b3,
    const float* __restrict__ sw, float* __restrict__ out)
{
    __shared__ float shW1T[3][8][32];    // [s][f][o]
    __shared__ float shB1[3][32];
    __shared__ float shW2T[3][32][16];   // [s][f][o]
    __shared__ float shB2[3][16];
    __shared__ float shW3[3][16];
    __shared__ float shB3[3];
    __shared__ float shSW[3];
    __shared__ float rs[8][8][8];        // [warp][row][stat]

    const int tid  = threadIdx.x;
    const int w    = tid >> 5;
    const int lane = tid & 31;

    // ---- One-time weight staging ----
    for (int idx = tid; idx < 768; idx += 256) {          // W1 [3][32][8]
        int s = idx >> 8, rem = idx & 255;
        shW1T[s][rem & 7][rem >> 3] = W1[idx];
    }
    for (int idx = tid; idx < 1536; idx += 256) {         // W2 [3][16][32]
        int s = idx >> 9, rem = idx & 511;
        shW2T[s][rem & 31][rem >> 5] = W2[idx];
    }
    if (tid < 96)                 ((float*)shB1)[tid] = b1[tid];
    else if (tid < 144)           ((float*)shB2)[tid - 96]  = b2[tid - 96];
    else if (tid < 192)           ((float*)shW3)[tid - 144] = W3[tid - 144];
    else if (tid < 195)           ((float*)shB3)[tid - 192] = b3[tid - 192];
    else if (tid >= 200 && tid < 203) shSW[tid - 200] = sw[tid - 200];
    __syncthreads();

    const int group = blockIdx.x * 8 + w;                 // 8192 groups
    const long long row0 = (long long)group * 8;

    const float invL  = 1.0f / (float)L_DIM;
    const float invN1 = 1.0f / (float)(L_DIM - 1);

    float* stg = stage_smem + w * 2048;   // this warp's two 1024-float stages

    // Chunk c (0..15): row = c>>1, tensor = c&1. 4KB per chunk.
    // Lane j copies/reads float4 elements j, j+32, ..., j+224 of the chunk.

    // ---- Prologue: issue chunks 0 and 1 ----
    #pragma unroll
    for (int c = 0; c < 2; c++) {
        const float* base = (c & 1) ? a2 : a1;
        const float4* s4 = (const float4*)(base + (row0 + (c >> 1)) * (long long)L_DIM);
        float4* d4 = (float4*)(stg + (c & 1) * 1024);
        #pragma unroll
        for (int i = 0; i < 8; i++)
            __pipeline_memcpy_async(&d4[lane + 32 * i], &s4[lane + 32 * i], 16);
        __pipeline_commit();
    }

    // ---- Main pipeline: wait chunk c, reduce it, issue chunk c+2 ----
    #pragma unroll
    for (int c = 0; c < 16; c++) {
        __pipeline_wait_prior(1);         // chunk c complete (c+1 still in flight)

        const float4* d4 = (const float4*)(stg + (c & 1) * 1024);
        float sa = 0.f, sb = 0.f, qa = 0.f, qb = 0.f;
        float mx = -FLT_MAX, mn = FLT_MAX;
        #pragma unroll
        for (int i = 0; i < 8; i++) {
            float4 v = d4[lane + 32 * i];
            if (i & 1) { sb += (v.x + v.y) + (v.z + v.w);
                         qb += (v.x * v.x + v.y * v.y) + (v.z * v.z + v.w * v.w); }
            else       { sa += (v.x + v.y) + (v.z + v.w);
                         qa += (v.x * v.x + v.y * v.y) + (v.z * v.z + v.w * v.w); }
            mx = fmaxf(mx, fmaxf(fmaxf(v.x, v.y), fmaxf(v.z, v.w)));
            mn = fminf(mn, fminf(fminf(v.x, v.y), fminf(v.z, v.w)));
        }

        // Issue chunk c+2 into the buffer we just finished reading.
        // Safe per-lane: lane j only reads the region lane j writes.
        if (c + 2 < 16) {
            int cn = c + 2;
            const float* base = (cn & 1) ? a2 : a1;
            const float4* s4 = (const float4*)(base + (row0 + (cn >> 1)) * (long long)L_DIM);
            float4* dn = (float4*)(stg + (cn & 1) * 1024);
            #pragma unroll
            for (int i = 0; i < 8; i++)
                __pipeline_memcpy_async(&dn[lane + 32 * i], &s4[lane + 32 * i], 16);
            __pipeline_commit();
        }

        // Reduce this chunk across the warp (loads for c+1/c+2 remain in flight).
        float s = sa + sb, q = qa + qb;
        #pragma unroll
        for (int off = 16; off > 0; off >>= 1) {
            s  += __shfl_xor_sync(0xffffffffu, s, off);
            q  += __shfl_xor_sync(0xffffffffu, q, off);
            mx  = fmaxf(mx, __shfl_xor_sync(0xffffffffu, mx, off));
            mn  = fminf(mn, __shfl_xor_sync(0xffffffffu, mn, off));
        }
        if (lane == 0) {
            const int r = c >> 1, t = (c & 1) * 4;
            rs[w][r][t + 0] = s;
            rs[w][r][t + 1] = sqrtf(fmaxf(0.f, (q - s * s * invL) * invN1));
            rs[w][r][t + 2] = mx;
            rs[w][r][t + 3] = mn;
        }
    }
    __syncwarp();

    // ---- Softmax over scale_weights ----
    float w0, w1g, w2g;
    {
        float t0 = shSW[0], t1 = shSW[1], t2 = shSW[2];
        float m  = fmaxf(t0, fmaxf(t1, t2));
        float e0 = __expf(t0 - m), e1 = __expf(t1 - m), e2 = __expf(t2 - m);
        float inv = 1.0f / (e0 + e1 + e2);
        w0 = e0 * inv; w1g = e1 * inv; w2g = e2 * inv;   // ws=2, ws=4, ws=8
    }

    // ---- Phase 2: 7 windows, lane-parallel MLPs ----
    float acc = 0.f;

    #pragma unroll
    for (int wi = 0; wi < 7; wi++) {
        int s, ws, r0;
        float wgt;
        if (wi == 0)      { s = 2; ws = 8; r0 = 0;            wgt = w2g; }
        else if (wi < 3)  { s = 1; ws = 4; r0 = (wi - 1) * 4; wgt = w1g; }
        else              { s = 0; ws = 2; r0 = (wi - 3) * 2; wgt = w0;  }

        const float invws = 1.0f / (float)ws;

        float g[8];
        {
            float sm1 = 0.f, sd1 = 0.f, sx1 = 0.f, sn1 = 0.f;
            float sm2 = 0.f, sd2 = 0.f, sx2 = 0.f, sn2 = 0.f;
            #pragma unroll
            for (int r = 0; r < 8; r++) {
                if (r >= r0 && r < r0 + ws) {
                    sm1 += rs[w][r][0]; sd1 += rs[w][r][1];
                    sx1 += rs[w][r][2]; sn1 += rs[w][r][3];
                    sm2 += rs[w][r][4]; sd2 += rs[w][r][5];
                    sx2 += rs[w][r][6]; sn2 += rs[w][r][7];
                }
            }
            g[0] = sm1 * invL * invws; g[1] = sd1 * invws;
            g[2] = sx1 * invws;        g[3] = sn1 * invws;
            g[4] = sm2 * invL * invws; g[5] = sd2 * invws;
            g[6] = sx2 * invws;        g[7] = sn2 * invws;
        }

        float h1;
        {
            float v = shB1[s][lane];
            #pragma unroll
            for (int f = 0; f < 8; f++) v = fmaf(shW1T[s][f][lane], g[f], v);
            h1 = fmaxf(v, 0.f);
        }
        float h2;
        {
            const int oo = lane & 15;
            float v = shB2[s][oo];
            #pragma unroll
            for (int f = 0; f < 32; f++)
                v = fmaf(shW2T[s][f][oo], __shfl_sync(0xffffffffu, h1, f), v);
            h2 = fmaxf(v, 0.f);
        }
        {
            float part = (lane < 16) ? shW3[s][lane] * h2 : 0.f;
            #pragma unroll
            for (int off = 16; off > 0; off >>= 1)
                part += __shfl_xor_sync(0xffffffffu, part, off);
            float z = __shfl_sync(0xffffffffu, part, 0) + shB3[s];
            float alpha = 1.0f / (1.0f + __expf(-z));
            if (lane >= r0 && lane < r0 + ws)
                acc = fmaf(wgt, alpha, acc);
        }
    }

    if (lane < 8)
        out[row0 + lane] = acc;
}

extern "C" void kernel_launch(void* const* d_in, const int* in_sizes, int n_in,
                              void* d_out, int out_size) {
    const float* a1 = (const float*)d_in[0];
    const float* a2 = (const float*)d_in[1];
    const float* W1 = (const float*)d_in[2];
    const float* b1 = (const float*)d_in[3];
    const float* W2 = (const float*)d_in[4];
    const float* b2 = (const float*)d_in[5];
    const float* W3 = (const float*)d_in[6];
    const float* b3 = (const float*)d_in[7];
    const float* sw = (const float*)d_in[8];
    float* out = (float*)d_out;

    const int dyn_smem = 8 * 2 * 1024 * (int)sizeof(float);   // 64KB
    cudaFuncSetAttribute(msdfg_kernel,
                         cudaFuncAttributeMaxDynamicSharedMemorySize, dyn_smem);

    const int groups = out_size / 8;     // 8192
    const int grid   = groups / 8;       // 1024 blocks, 8 warps each
    msdfg_kernel<<<grid, 256, dyn_smem>>>(a1, a2, W1, b1, W2, b2, W3, b3, sw, out);
}